// round 7
// baseline (speedup 1.0000x reference)
#include <cuda_runtime.h>
#include <cstdint>

// TopKRouter: B=4, T=8192, C=1024, E=8, K=2.  (passed R5 @77us, L1-bound)
// R6 (retry; previous round was an infra failure, kernel never ran):
// register-blocked 2 rows x 8 experts per thread, smem-staged x,
// warp-uniform W loads. Each output keeps the proven sequential fmaf chain
// over k ascending (bit-identical to R5 => selection identical).
// Output (fp32): [router_output (262144)] [top_idx-as-float (65536)]

#define NE    8
#define NC4   256                       // float4 per row (C=1024)
#define ROWS_PER_BLOCK 256
#define THREADS 128
#define GRID  128                       // 32768 / 256
#define KC4   4                         // float4 per row per chunk (64 floats)
#define NCHUNK 64                       // 256 / 4
#define XSTRIDE 5                       // padded row stride (float4) in smem
#define XBUF  (ROWS_PER_BLOCK * XSTRIDE)   // 1280 float4 per buffer
#define SMEM_F4 (NE * NC4 + 2 * XBUF)      // 2048 + 2560 = 4608 float4
#define SMEM_BYTES (SMEM_F4 * 16)          // 73728 B
#define OUTP_ELEMS (32768 * NE)

extern __shared__ float4 smem_dyn[];

__device__ __forceinline__ void finish_row(const float* acc, int row,
                                           float* __restrict__ out)
{
    // max: order-independent
    float mx = acc[0];
    #pragma unroll
    for (int e = 1; e < 8; e++) mx = fmaxf(mx, acc[e]);
    float ex[8];
    #pragma unroll
    for (int e = 0; e < 8; e++) ex[e] = expf(acc[e] - mx);
    // tree sum replicating the R5 8-lane butterfly order (bit-exact)
    const float s01 = ex[0] + ex[1], s23 = ex[2] + ex[3];
    const float s45 = ex[4] + ex[5], s67 = ex[6] + ex[7];
    const float sm = (s01 + s23) + (s45 + s67);
    float p[8];
    #pragma unroll
    for (int e = 0; e < 8; e++) p[e] = ex[e] / sm;
    // top-1 then top-2, lowest index wins ties (ascending scan, strict >)
    int bi = 0; float bv = p[0];
    #pragma unroll
    for (int e = 1; e < 8; e++) if (p[e] > bv) { bv = p[e]; bi = e; }
    int bi2 = -1; float bv2 = -1.0f;
    #pragma unroll
    for (int e = 0; e < 8; e++)
        if (e != bi && p[e] > bv2) { bv2 = p[e]; bi2 = e; }

    float oo[8];
    #pragma unroll
    for (int e = 0; e < 8; e++) oo[e] = (e == bi || e == bi2) ? p[e] : 0.0f;
    float4* op = reinterpret_cast<float4*>(out + (size_t)row * 8);
    op[0] = make_float4(oo[0], oo[1], oo[2], oo[3]);
    op[1] = make_float4(oo[4], oo[5], oo[6], oo[7]);
    float2* ip = reinterpret_cast<float2*>(out + OUTP_ELEMS + (size_t)row * 2);
    *ip = make_float2((float)bi, (float)bi2);
}

__global__ __launch_bounds__(THREADS, 1)
void router_kernel(const float* __restrict__ x,
                   const float* __restrict__ W,
                   float* __restrict__ out)
{
    float4* ws = smem_dyn;                 // W: [e*256 + k4], 32 KB
    float4* xs = smem_dyn + NE * NC4;      // x: 2 buffers of 1280 f4 (stride-5 rows)

    const int t = threadIdx.x;

    // --- stage W (coalesced, once) ---
    const float4* w4 = reinterpret_cast<const float4*>(W);
    #pragma unroll
    for (int s = 0; s < 16; s++) ws[t + 128 * s] = w4[t + 128 * s];

    const int row0 = blockIdx.x * ROWS_PER_BLOCK;
    const float4* xg = reinterpret_cast<const float4*>(x);

    // staging pattern (constant per thread): 8 rows-apart-32, fixed col jj
    const int jj = t & 3;
    const int rbase = t >> 2;

    float4 tmp[8];
    // prologue: stage chunk 0
    #pragma unroll
    for (int s = 0; s < 8; s++)
        tmp[s] = __ldg(&xg[(size_t)(row0 + rbase + 32 * s) * NC4 + jj]);
    #pragma unroll
    for (int s = 0; s < 8; s++)
        xs[(rbase + 32 * s) * XSTRIDE + jj] = tmp[s];
    __syncthreads();

    float accA[8], accB[8];
    #pragma unroll
    for (int e = 0; e < 8; e++) { accA[e] = 0.0f; accB[e] = 0.0f; }

    for (int c = 0; c < NCHUNK; c++) {
        // issue next chunk's global loads early (latency overlapped w/ compute)
        if (c + 1 < NCHUNK) {
            #pragma unroll
            for (int s = 0; s < 8; s++)
                tmp[s] = __ldg(&xg[(size_t)(row0 + rbase + 32 * s) * NC4
                                   + (c + 1) * KC4 + jj]);
        }
        const float4* xb = xs + (c & 1) * XBUF;
        const float4* xA = xb + t * XSTRIDE;              // row  t
        const float4* xB = xb + (t + 128) * XSTRIDE;      // row  t+128
        #pragma unroll
        for (int j = 0; j < KC4; j++) {
            const float4 a = xA[j];
            const float4 b = xB[j];
            const int k4 = c * KC4 + j;
            #pragma unroll
            for (int e = 0; e < 8; e++) {
                const float4 wv = ws[e * NC4 + k4];       // warp-uniform
                float va = accA[e];
                va = fmaf(a.x, wv.x, va); va = fmaf(a.y, wv.y, va);
                va = fmaf(a.z, wv.z, va); va = fmaf(a.w, wv.w, va);
                accA[e] = va;
                float vb = accB[e];
                vb = fmaf(b.x, wv.x, vb); vb = fmaf(b.y, wv.y, vb);
                vb = fmaf(b.z, wv.z, vb); vb = fmaf(b.w, wv.w, vb);
                accB[e] = vb;
            }
        }
        if (c + 1 < NCHUNK) {
            float4* xw = xs + ((c + 1) & 1) * XBUF;
            #pragma unroll
            for (int s = 0; s < 8; s++)
                xw[(rbase + 32 * s) * XSTRIDE + jj] = tmp[s];
        }
        __syncthreads();
    }

    finish_row(accA, row0 + t, out);
    finish_row(accB, row0 + t + 128, out);
}

extern "C" void kernel_launch(void* const* d_in, const int* in_sizes, int n_in,
                              void* d_out, int out_size)
{
    const float* x = (const float*)d_in[0];
    const float* W = (const float*)d_in[1];
    if (n_in >= 2 && in_sizes[0] < in_sizes[1]) {   // safety: (x, W) order
        x = (const float*)d_in[1];
        W = (const float*)d_in[0];
    }
    cudaFuncSetAttribute(router_kernel,
                         cudaFuncAttributeMaxDynamicSharedMemorySize, SMEM_BYTES);
    router_kernel<<<GRID, THREADS, SMEM_BYTES>>>(x, W, (float*)d_out);
}

// round 8
// speedup vs baseline: 1.3450x; 1.3450x over previous
#include <cuda_runtime.h>
#include <cstdint>

// TopKRouter: B=4, T=8192, C=1024, E=8, K=2.
// R7 = R5 thread-mapping (proven bit-exact, 5.64e-7) + smem-staged x + high occupancy.
//   warp = 4 rows x 8 experts; lane: j=lane>>3 (row), e=lane&7 (expert).
//   x: GMEM -> smem (double-buffered, 1 LDG.128/thread/chunk), read as 8-lane broadcast.
//   W: smem, padded stride 257 f4 -> conflict-free across the 8 experts.
// Output (fp32): [router_output (262144)] [top_idx-as-float (65536)]

#define NE     8
#define NC4    256                    // float4 per row (C=1024)
#define WPAD   257                    // padded f4 stride for W rows in smem
#define THREADS 256                   // 8 warps
#define ROWS_PER_BLOCK 32
#define GRID   1024                   // 32768 / 32
#define KC4    8                      // f4 per row per chunk (32 floats)
#define NCHUNK 32                     // 256 / 8
#define XS     9                      // padded f4 stride for x rows in smem
#define XBUF   (ROWS_PER_BLOCK * XS)  // 288 f4 per buffer
#define SMEM_F4 (NE * WPAD + 2 * XBUF)   // 2056 + 576 = 2632 f4
#define SMEM_BYTES (SMEM_F4 * 16)        // 42112 B
#define OUTP_ELEMS (32768 * NE)

extern __shared__ float4 smem_dyn[];

__global__ __launch_bounds__(THREADS, 1)
void router_kernel(const float* __restrict__ x,
                   const float* __restrict__ W,
                   float* __restrict__ out)
{
    float4* ws = smem_dyn;             // W: ws[e*WPAD + k4]
    float4* xs = smem_dyn + NE * WPAD; // x: 2 buffers of XBUF f4 (stride-XS rows)

    const int t = threadIdx.x;
    const int lane = t & 31;
    const int warp = t >> 5;

    // --- stage W (8 x 256 f4), coalesced, into padded layout ---
    const float4* w4 = reinterpret_cast<const float4*>(W);
    #pragma unroll
    for (int s = 0; s < 8; s++) {
        const int i = t + 256 * s;         // 0..2047
        ws[(i >> 8) * WPAD + (i & 255)] = w4[i];
    }

    const int row0 = blockIdx.x * ROWS_PER_BLOCK;
    const float4* xg = reinterpret_cast<const float4*>(x);

    // staging: thread t loads row (t>>3), f4 col (t&7) of each chunk (1 LDG.128)
    const int srow = t >> 3;               // 0..31
    const int scol = t & 7;                // 0..7

    // prologue: stage chunk 0
    float4 tmp = __ldg(&xg[(size_t)(row0 + srow) * NC4 + scol]);
    xs[srow * XS + scol] = tmp;
    __syncthreads();

    // compute mapping: lane j = row-in-4-group, e = expert
    const int j = lane >> 3;
    const int e = lane & 7;
    const int lrow = warp * 4 + j;         // block-local row 0..31
    const int row  = row0 + lrow;
    const float4* wp = ws + e * WPAD;

    float acc = 0.0f;                      // sequential fmaf chain, k ascending
    for (int c = 0; c < NCHUNK; c++) {
        if (c + 1 < NCHUNK)
            tmp = __ldg(&xg[(size_t)(row0 + srow) * NC4 + (c + 1) * KC4 + scol]);

        const float4* xb = xs + (c & 1) * XBUF + lrow * XS;
        #pragma unroll
        for (int q = 0; q < KC4; q++) {
            const float4 xv = xb[q];                 // 8-lane broadcast groups
            const float4 wv = wp[c * KC4 + q];       // conflict-free (WPAD)
            acc = fmaf(xv.x, wv.x, acc);
            acc = fmaf(xv.y, wv.y, acc);
            acc = fmaf(xv.z, wv.z, acc);
            acc = fmaf(xv.w, wv.w, acc);
        }
        if (c + 1 < NCHUNK)
            xs[((c + 1) & 1) * XBUF + srow * XS + scol] = tmp;
        __syncthreads();
    }
    const float logit = acc;

    // --- softmax over the 8-lane expert group (R5-verbatim, bit-exact) ---
    float mx = logit;
    #pragma unroll
    for (int m = 1; m < 8; m <<= 1)
        mx = fmaxf(mx, __shfl_xor_sync(0xffffffffu, mx, m));
    const float ex = expf(logit - mx);
    float sm = ex;
    #pragma unroll
    for (int m = 1; m < 8; m <<= 1)
        sm += __shfl_xor_sync(0xffffffffu, sm, m);
    const float prob = ex / sm;

    // --- top-1 then top-2, lowest index wins ties (R5-verbatim) ---
    float bv = prob; int bi = e;
    #pragma unroll
    for (int m = 1; m < 8; m <<= 1) {
        float ov = __shfl_xor_sync(0xffffffffu, bv, m);
        int   oi = __shfl_xor_sync(0xffffffffu, bi, m);
        if (ov > bv || (ov == bv && oi < bi)) { bv = ov; bi = oi; }
    }
    float bv2 = (e == bi) ? -1.0f : prob; int bi2 = e;
    #pragma unroll
    for (int m = 1; m < 8; m <<= 1) {
        float ov = __shfl_xor_sync(0xffffffffu, bv2, m);
        int   oi = __shfl_xor_sync(0xffffffffu, bi2, m);
        if (ov > bv2 || (ov == bv2 && oi < bi2)) { bv2 = ov; bi2 = oi; }
    }

    // --- store 0: router_output, coalesced 128B per warp ---
    const float o = (e == bi || e == bi2) ? prob : 0.0f;
    out[(size_t)row * NE + e] = o;

    // --- store 1: top_idx as float (harness output dtype is fp32) ---
    if (e < 2) {
        const int v = (e == 0) ? bi : bi2;   // argmax first
        out[OUTP_ELEMS + (size_t)row * 2 + e] = (float)v;
    }
}

extern "C" void kernel_launch(void* const* d_in, const int* in_sizes, int n_in,
                              void* d_out, int out_size)
{
    const float* x = (const float*)d_in[0];
    const float* W = (const float*)d_in[1];
    if (n_in >= 2 && in_sizes[0] < in_sizes[1]) {   // safety: (x, W) order
        x = (const float*)d_in[1];
        W = (const float*)d_in[0];
    }
    cudaFuncSetAttribute(router_kernel,
                         cudaFuncAttributeMaxDynamicSharedMemorySize, SMEM_BYTES);
    router_kernel<<<GRID, THREADS, SMEM_BYTES>>>(x, W, (float*)d_out);
}